// round 2
// baseline (speedup 1.0000x reference)
#include <cuda_runtime.h>
#include <math.h>

#define T 4096
#define H 128
#define HH (H*H)
#define C 128
#define NC (T/C)   // 32
#define L 2

// ---------------- scratch (device globals; no allocation allowed) ------------
__device__ float g_x[T*H];
__device__ float g_q[T*H];
__device__ float g_k[T*H];
__device__ float g_v[T*H];
__device__ float g_z[T*H];
__device__ float g_kv[NC*HH];   // per-chunk KV tail sums
__device__ float g_S[NC*HH];    // state before each chunk
__device__ int   g_rloc[T];     // last reset index within chunk (local), -1 if none
__device__ int   g_cs0[NC];     // chunk tail-sum start (local)
__device__ int   g_crst[NC];    // chunk has reset flag

// ---------------- reset preprocessing ----------------------------------------
__global__ void reset_kernel(const unsigned char* __restrict__ start) {
    __shared__ unsigned char f[C];
    int c = blockIdx.x, t = threadIdx.x;
    f[t] = start[c*C + t];
    __syncthreads();
    int r = -1;
    for (int j = t; j >= 0; --j) { if (f[j]) { r = j; break; } }
    g_rloc[c*C + t] = r;
    if (t == C-1) { g_cs0[c] = (r >= 0) ? r : 0; g_crst[c] = (r >= 0) ? 1 : 0; }
}

// ---------------- generic GEMM: out[t,n] = act(sum_k A[t,k]*W[n,k] + b[n]) ----
// ACT: 0 none, 1 phi (1+elu), 2 leaky_relu(0.01)
template<int ACT>
__global__ void gemm_tn(const float* __restrict__ A, const float* __restrict__ W,
                        const float* __restrict__ b, float* __restrict__ out) {
    __shared__ float As[32][33];
    __shared__ float Ws[128][33];
    int t0 = blockIdx.x * 32;
    int tid = threadIdx.x;
    int ty = tid >> 4, tx = tid & 15;       // 16x16
    float acc[2][8];
    #pragma unroll
    for (int i = 0; i < 2; i++)
        #pragma unroll
        for (int j = 0; j < 8; j++) acc[i][j] = 0.f;

    for (int kk = 0; kk < H; kk += 32) {
        #pragma unroll
        for (int i = 0; i < 4; i++) {
            int lin = tid + i*256;
            int r = lin >> 5, cc = lin & 31;
            As[r][cc] = A[(t0 + r)*H + kk + cc];
        }
        #pragma unroll
        for (int i = 0; i < 16; i++) {
            int lin = tid + i*256;
            int n = lin >> 5, cc = lin & 31;
            Ws[n][cc] = W[n*H + kk + cc];
        }
        __syncthreads();
        #pragma unroll
        for (int k = 0; k < 32; k++) {
            float a[2], w[8];
            #pragma unroll
            for (int i = 0; i < 2; i++) a[i] = As[ty*2+i][k];
            #pragma unroll
            for (int j = 0; j < 8; j++) w[j] = Ws[tx*8+j][k];
            #pragma unroll
            for (int i = 0; i < 2; i++)
                #pragma unroll
                for (int j = 0; j < 8; j++) acc[i][j] += a[i]*w[j];
        }
        __syncthreads();
    }
    #pragma unroll
    for (int i = 0; i < 2; i++) {
        int t = t0 + ty*2 + i;
        #pragma unroll
        for (int j = 0; j < 8; j++) {
            int n = tx*8 + j;
            float v = acc[i][j] + (b ? b[n] : 0.f);
            if (ACT == 1) v = (v > 0.f) ? (1.f + v) : expf(v);
            if (ACT == 2) v = (v > 0.f) ? v : 0.01f * v;
            out[t*H + n] = v;
        }
    }
}

// ---------------- per-chunk KV tail sums: g_kv[c] = K_tail^T @ V -------------
__global__ void chunk_kv_kernel() {
    __shared__ float Ks[32][129];
    __shared__ float Vs[32][129];
    int c = blockIdx.x;
    int s0 = g_cs0[c];
    int tid = threadIdx.x;
    int ty = tid >> 4, tx = tid & 15;   // out rows kk=ty*8+i (128), cols vv=tx*8+j (128)
    float acc[8][8];
    #pragma unroll
    for (int i = 0; i < 8; i++)
        #pragma unroll
        for (int j = 0; j < 8; j++) acc[i][j] = 0.f;
    int base = c*C*H;
    for (int ss = 0; ss < C; ss += 32) {
        #pragma unroll
        for (int i = 0; i < 16; i++) {
            int lin = tid + i*256;
            int s = lin >> 7, n = lin & 127;
            float kval = g_k[base + (ss+s)*H + n];
            float vval = g_v[base + (ss+s)*H + n];
            Ks[s][n] = ((ss + s) >= s0) ? kval : 0.f;
            Vs[s][n] = vval;
        }
        __syncthreads();
        #pragma unroll
        for (int s = 0; s < 32; s++) {
            float kf[8], vf[8];
            #pragma unroll
            for (int i = 0; i < 8; i++) kf[i] = Ks[s][ty*8+i];
            #pragma unroll
            for (int j = 0; j < 8; j++) vf[j] = Vs[s][tx*8+j];
            #pragma unroll
            for (int i = 0; i < 8; i++)
                #pragma unroll
                for (int j = 0; j < 8; j++) acc[i][j] += kf[i]*vf[j];
        }
        __syncthreads();
    }
    #pragma unroll
    for (int i = 0; i < 8; i++)
        #pragma unroll
        for (int j = 0; j < 8; j++)
            g_kv[c*HH + (ty*8+i)*H + tx*8+j] = acc[i][j];
}

// ---------------- inter-chunk scan (resettable) ------------------------------
__global__ void scan_kernel() {
    int idx0 = blockIdx.x * 512 + threadIdx.x;   // 32 blocks x 128 threads
    float S[4], kv[4], kvn[4];
    #pragma unroll
    for (int e = 0; e < 4; e++) { S[e] = 0.f; kv[e] = g_kv[idx0 + e*128]; kvn[e] = 0.f; }
    for (int c = 0; c < NC; c++) {
        int rst = g_crst[c];
        if (c + 1 < NC) {
            #pragma unroll
            for (int e = 0; e < 4; e++) kvn[e] = g_kv[(c+1)*HH + idx0 + e*128];
        }
        #pragma unroll
        for (int e = 0; e < 4; e++) {
            g_S[c*HH + idx0 + e*128] = S[e];
            S[e] = (rst ? 0.f : S[e]) + kv[e];
            kv[e] = kvn[e];
        }
    }
}

// ---------------- intra-chunk attention + residual ---------------------------
// block handles 32 t-rows of one chunk; grid = NC*4 = 128
__global__ void attn_kernel() {
    __shared__ float P[32][132];
    __shared__ float TaBuf[128*33];   // reused: K tile [128][33], V/S tiles [32][132]
    __shared__ float Tq[32][33];
    __shared__ float den_s[32];
    __shared__ int rl_s[32];

    int bx = blockIdx.x;
    int c  = bx >> 2;
    int tb = (bx & 3) * 32;           // local t base within chunk
    int cbase = c * C;
    int tid = threadIdx.x;
    int ty = tid >> 4, tx = tid & 15;

    if (tid < 32) rl_s[tid] = g_rloc[cbase + tb + tid];

    // Stage A: P[tl][s] = q_t . k_s over k-dim
    float accA[2][8];
    #pragma unroll
    for (int i = 0; i < 2; i++)
        #pragma unroll
        for (int j = 0; j < 8; j++) accA[i][j] = 0.f;

    for (int kk = 0; kk < H; kk += 32) {
        #pragma unroll
        for (int i = 0; i < 4; i++) {
            int lin = tid + i*256;
            int r = lin >> 5, cc = lin & 31;
            Tq[r][cc] = g_q[(cbase + tb + r)*H + kk + cc];
        }
        #pragma unroll
        for (int i = 0; i < 16; i++) {
            int lin = tid + i*256;
            int r = lin >> 5, cc = lin & 31;
            TaBuf[r*33 + cc] = g_k[(cbase + r)*H + kk + cc];
        }
        __syncthreads();
        #pragma unroll
        for (int k = 0; k < 32; k++) {
            float qf[2], kf[8];
            #pragma unroll
            for (int i = 0; i < 2; i++) qf[i] = Tq[ty*2+i][k];
            #pragma unroll
            for (int j = 0; j < 8; j++) kf[j] = TaBuf[(tx*8+j)*33 + k];
            #pragma unroll
            for (int i = 0; i < 2; i++)
                #pragma unroll
                for (int j = 0; j < 8; j++) accA[i][j] += qf[i]*kf[j];
        }
        __syncthreads();
    }
    // mask + den + write P
    #pragma unroll
    for (int i = 0; i < 2; i++) {
        int rl = rl_s[ty*2+i];
        int lo = (rl < 0) ? 0 : rl;
        int tl = tb + ty*2 + i;       // local 0..127
        #pragma unroll
        for (int j = 0; j < 8; j++) {
            int s = tx*8 + j;
            float val = accA[i][j];
            if (s == tl) den_s[ty*2+i] = 1e-6f + val;
            P[ty*2+i][s] = (s >= lo && s <= tl) ? val : 0.f;
        }
    }

    // Stage B: acc = P @ V + gate * Q @ S_before
    float acc[2][8];
    #pragma unroll
    for (int i = 0; i < 2; i++)
        #pragma unroll
        for (int j = 0; j < 8; j++) acc[i][j] = 0.f;

    // B1: P @ V over s
    for (int ss = 0; ss < C; ss += 32) {
        __syncthreads();
        #pragma unroll
        for (int i = 0; i < 16; i++) {
            int lin = tid + i*256;
            int s2 = lin >> 7, v = lin & 127;
            TaBuf[s2*132 + v] = g_v[(cbase + ss + s2)*H + v];
        }
        __syncthreads();
        #pragma unroll
        for (int s2 = 0; s2 < 32; s2++) {
            float pf[2], vf[8];
            #pragma unroll
            for (int i = 0; i < 2; i++) pf[i] = P[ty*2+i][ss+s2];
            #pragma unroll
            for (int j = 0; j < 8; j++) vf[j] = TaBuf[s2*132 + tx*8+j];
            #pragma unroll
            for (int i = 0; i < 2; i++)
                #pragma unroll
                for (int j = 0; j < 8; j++) acc[i][j] += pf[i]*vf[j];
        }
    }

    // B2: gated Q @ S_before
    float u[2];
    #pragma unroll
    for (int i = 0; i < 2; i++) u[i] = (rl_s[ty*2+i] < 0) ? 1.f : 0.f;
    for (int kk = 0; kk < H; kk += 32) {
        __syncthreads();
        #pragma unroll
        for (int i = 0; i < 4; i++) {
            int lin = tid + i*256;
            int r = lin >> 5, cc = lin & 31;
            Tq[r][cc] = g_q[(cbase + tb + r)*H + kk + cc];
        }
        #pragma unroll
        for (int i = 0; i < 16; i++) {
            int lin = tid + i*256;
            int kr = lin >> 7, v = lin & 127;
            TaBuf[kr*132 + v] = g_S[c*HH + (kk+kr)*H + v];
        }
        __syncthreads();
        #pragma unroll
        for (int k2 = 0; k2 < 32; k2++) {
            float qf[2], sf[8];
            #pragma unroll
            for (int i = 0; i < 2; i++) qf[i] = Tq[ty*2+i][k2] * u[i];
            #pragma unroll
            for (int j = 0; j < 8; j++) sf[j] = TaBuf[k2*132 + tx*8+j];
            #pragma unroll
            for (int i = 0; i < 2; i++)
                #pragma unroll
                for (int j = 0; j < 8; j++) acc[i][j] += qf[i]*sf[j];
        }
    }

    // epilogue: z = num/den + x
    #pragma unroll
    for (int i = 0; i < 2; i++) {
        int tg = cbase + tb + ty*2 + i;
        float d = den_s[ty*2+i];
        #pragma unroll
        for (int j = 0; j < 8; j++) {
            int v = tx*8 + j;
            g_z[tg*H + v] = acc[i][j] / d + g_x[tg*H + v];
        }
    }
}

// ---------------- launch ------------------------------------------------------
extern "C" void kernel_launch(void* const* d_in, const int* in_sizes, int n_in,
                              void* d_out, int out_size) {
    const float* emb          = (const float*)d_in[0];
    const unsigned char* start= (const unsigned char*)d_in[1];
    const float* W_in         = (const float*)d_in[2];
    const float* b_in         = (const float*)d_in[3];
    const float* W_q          = (const float*)d_in[4];
    const float* W_k          = (const float*)d_in[5];
    const float* W_v          = (const float*)d_in[6];
    const float* W_ff         = (const float*)d_in[7];
    const float* b_ff         = (const float*)d_in[8];
    const float* W_out        = (const float*)d_in[9];
    const float* b_out        = (const float*)d_in[10];
    float* out = (float*)d_out;

    float *px, *pq, *pk, *pv, *pz;
    cudaGetSymbolAddress((void**)&px, g_x);
    cudaGetSymbolAddress((void**)&pq, g_q);
    cudaGetSymbolAddress((void**)&pk, g_k);
    cudaGetSymbolAddress((void**)&pv, g_v);
    cudaGetSymbolAddress((void**)&pz, g_z);

    reset_kernel<<<NC, C>>>(start);
    gemm_tn<0><<<T/32, 256>>>(emb, W_in, b_in, px);

    for (int l = 0; l < L; l++) {
        gemm_tn<1><<<T/32, 256>>>(px, W_q + l*HH, nullptr, pq);
        gemm_tn<1><<<T/32, 256>>>(px, W_k + l*HH, nullptr, pk);
        gemm_tn<0><<<T/32, 256>>>(px, W_v + l*HH, nullptr, pv);
        chunk_kv_kernel<<<NC, 256>>>();
        scan_kernel<<<NC, 128>>>();
        attn_kernel<<<NC*4, 256>>>();
        gemm_tn<2><<<T/32, 256>>>(pz, W_ff + l*HH, b_ff + l*H, px);
    }
    gemm_tn<0><<<T/32, 256>>>(px, W_out, b_out, out);
}

// round 3
// speedup vs baseline: 2.2552x; 2.2552x over previous
#include <cuda_runtime.h>
#include <math.h>

#define T 4096
#define H 128
#define HH (H*H)
#define C 128
#define NC (T/C)   // 32
#define L 2

// ---------------- scratch (device globals; no allocation allowed) ------------
__device__ float g_x[T*H];
__device__ float g_q[T*H];
__device__ float g_k[T*H];
__device__ float g_kT[T*H];      // per-chunk transposed K: [c][k][s_local]
__device__ float g_v[T*H];
__device__ float g_z[T*H];
__device__ float g_Wt[10*HH];    // transposed weights [k][n]
__device__ float g_kvp[4*NC*HH]; // per-(chunk,quarter) KV partial sums
__device__ float g_S[NC*HH];     // state before each chunk
__device__ int   g_rloc[T];      // last reset index within chunk (local), -1 if none
__device__ int   g_cs0[NC];      // chunk tail-sum start (local)
__device__ int   g_crst[NC];     // chunk has reset flag

#define SMG ((128*128 + 32*128)*4)
#define SMA ((128*128 + 32*128 + 32*128)*4)

// ---------------- reset preprocessing ----------------------------------------
__global__ void reset_kernel(const unsigned char* __restrict__ start) {
    __shared__ unsigned char f[C];
    int c = blockIdx.x, t = threadIdx.x;
    f[t] = start[c*C + t];
    __syncthreads();
    int r = -1;
    for (int j = t; j >= 0; --j) { if (f[j]) { r = j; break; } }
    g_rloc[c*C + t] = r;
    if (t == C-1) { g_cs0[c] = (r >= 0) ? r : 0; g_crst[c] = (r >= 0) ? 1 : 0; }
}

// ---------------- weight transpose: g_Wt[z][k][n] = W_z[n][k] -----------------
__global__ void wt_kernel(const float* __restrict__ W_in, const float* __restrict__ W_q,
                          const float* __restrict__ W_k, const float* __restrict__ W_v,
                          const float* __restrict__ W_ff, const float* __restrict__ W_out) {
    __shared__ float tile[32][33];
    int z = blockIdx.z;
    const float* src;
    switch (z) {
        case 0: src = W_in; break;
        case 1: src = W_q; break;
        case 2: src = W_k; break;
        case 3: src = W_v; break;
        case 4: src = W_q + HH; break;
        case 5: src = W_k + HH; break;
        case 6: src = W_v + HH; break;
        case 7: src = W_ff; break;
        case 8: src = W_ff + HH; break;
        default: src = W_out; break;
    }
    float* dst = g_Wt + z*HH;
    int k0 = blockIdx.x*32, n0 = blockIdx.y*32;
    int tx = threadIdx.x, ty = threadIdx.y;   // (32,8)
    #pragma unroll
    for (int i = 0; i < 4; i++)
        tile[ty + 8*i][tx] = src[(n0 + ty + 8*i)*H + k0 + tx];
    __syncthreads();
    #pragma unroll
    for (int i = 0; i < 4; i++)
        dst[(k0 + ty + 8*i)*H + n0 + tx] = tile[tx][ty + 8*i];
}

// ---------------- GEMM: out[t,n] = act(sum_k A[t,k]*Wt[k,n] + b[n]) ----------
// ACT: 0 none, 2 leaky_relu(0.01)
template<int ACT>
__global__ __launch_bounds__(256) void gemm32(const float* __restrict__ A,
                                              const float* __restrict__ Wt,
                                              const float* __restrict__ b,
                                              float* __restrict__ out) {
    extern __shared__ float sm[];
    float* Ws = sm;               // [k][n] 128x128
    float* As = sm + 128*128;     // [r][k] 32x128
    int tid = threadIdx.x;
    int t0 = blockIdx.x * 32;
    {
        const float4* Wt4 = (const float4*)Wt;
        float4* Ws4 = (float4*)Ws;
        #pragma unroll
        for (int it = 0; it < 16; it++) Ws4[tid + it*256] = Wt4[tid + it*256];
        const float4* A4 = (const float4*)(A + t0*H);
        float4* As4 = (float4*)As;
        #pragma unroll
        for (int it = 0; it < 4; it++) As4[tid + it*256] = A4[tid + it*256];
    }
    __syncthreads();
    int gt = tid >> 5, gs = tid & 31;   // rows gt*4+i (32), cols gs*4+j (128)
    float acc[4][4] = {};
    #pragma unroll 16
    for (int k = 0; k < 128; k++) {
        float4 w = *(const float4*)&Ws[k*128 + gs*4];
        #pragma unroll
        for (int i = 0; i < 4; i++) {
            float a = As[(gt*4+i)*128 + k];
            acc[i][0] += a*w.x; acc[i][1] += a*w.y;
            acc[i][2] += a*w.z; acc[i][3] += a*w.w;
        }
    }
    float4 bb = make_float4(0.f,0.f,0.f,0.f);
    if (b) bb = *(const float4*)&b[gs*4];
    #pragma unroll
    for (int i = 0; i < 4; i++) {
        float4 r;
        r.x = acc[i][0] + bb.x; r.y = acc[i][1] + bb.y;
        r.z = acc[i][2] + bb.z; r.w = acc[i][3] + bb.w;
        if (ACT == 2) {
            r.x = (r.x > 0.f) ? r.x : 0.01f*r.x;
            r.y = (r.y > 0.f) ? r.y : 0.01f*r.y;
            r.z = (r.z > 0.f) ? r.z : 0.01f*r.z;
            r.w = (r.w > 0.f) ? r.w : 0.01f*r.w;
        }
        *(float4*)&out[(t0 + gt*4 + i)*H + gs*4] = r;
    }
}

// ---------------- fused QKV GEMM (grid.y selects q/k/v) -----------------------
__device__ __forceinline__ float phi_f(float v) {
    return (v > 0.f) ? (1.f + v) : __expf(v);
}

__global__ __launch_bounds__(256) void qkv_kernel(const float* __restrict__ A,
        const float* __restrict__ Wtq, const float* __restrict__ Wtk,
        const float* __restrict__ Wtv) {
    extern __shared__ float sm[];
    float* Ws = sm;
    float* As = sm + 128*128;
    int tid = threadIdx.x;
    int t0 = blockIdx.x * 32;
    int y = blockIdx.y;
    const float* Wt = (y == 0) ? Wtq : (y == 1) ? Wtk : Wtv;
    {
        const float4* Wt4 = (const float4*)Wt;
        float4* Ws4 = (float4*)Ws;
        #pragma unroll
        for (int it = 0; it < 16; it++) Ws4[tid + it*256] = Wt4[tid + it*256];
        const float4* A4 = (const float4*)(A + t0*H);
        float4* As4 = (float4*)As;
        #pragma unroll
        for (int it = 0; it < 4; it++) As4[tid + it*256] = A4[tid + it*256];
    }
    __syncthreads();
    int gt = tid >> 5, gs = tid & 31;
    float acc[4][4] = {};
    #pragma unroll 16
    for (int k = 0; k < 128; k++) {
        float4 w = *(const float4*)&Ws[k*128 + gs*4];
        #pragma unroll
        for (int i = 0; i < 4; i++) {
            float a = As[(gt*4+i)*128 + k];
            acc[i][0] += a*w.x; acc[i][1] += a*w.y;
            acc[i][2] += a*w.z; acc[i][3] += a*w.w;
        }
    }
    float* out = (y == 0) ? g_q : (y == 1) ? g_k : g_v;
    #pragma unroll
    for (int i = 0; i < 4; i++) {
        int t = t0 + gt*4 + i;
        float4 r;
        if (y < 2) {
            r.x = phi_f(acc[i][0]); r.y = phi_f(acc[i][1]);
            r.z = phi_f(acc[i][2]); r.w = phi_f(acc[i][3]);
        } else {
            r.x = acc[i][0]; r.y = acc[i][1]; r.z = acc[i][2]; r.w = acc[i][3];
        }
        *(float4*)&out[t*H + gs*4] = r;
        if (y == 1) {
            int c = t >> 7, sl = t & 127;
            float* kT = g_kT + c*HH + sl;
            kT[(gs*4+0)*128] = r.x;
            kT[(gs*4+1)*128] = r.y;
            kT[(gs*4+2)*128] = r.z;
            kT[(gs*4+3)*128] = r.w;
        }
    }
}

// ---------------- per-chunk-quarter KV partials: g_kvp = K_q^T @ V_q ---------
__global__ __launch_bounds__(256) void chunk_kv_kernel() {
    __shared__ float Ks[32*128];
    __shared__ float Vs[32*128];
    int bx = blockIdx.x;
    int c = bx >> 2, qi = bx & 3;
    int s0 = g_cs0[c];
    int tid = threadIdx.x;
    int base = (c*C + qi*32) * H;
    {
        const float4* K4 = (const float4*)(g_k + base);
        const float4* V4 = (const float4*)(g_v + base);
        float4* Ks4 = (float4*)Ks;
        float4* Vs4 = (float4*)Vs;
        #pragma unroll
        for (int it = 0; it < 4; it++) {
            int idx = tid + it*256;
            int srow = idx >> 5;        // local s
            float4 kv4 = K4[idx];
            if (qi*32 + srow < s0) kv4 = make_float4(0.f,0.f,0.f,0.f);
            Ks4[idx] = kv4;
            Vs4[idx] = V4[idx];
        }
    }
    __syncthreads();
    int ty = tid >> 4, tx = tid & 15;   // kk rows ty*8+i, vv cols tx*8+j
    float acc[8][8] = {};
    #pragma unroll 4
    for (int s = 0; s < 32; s++) {
        float4 k0 = *(const float4*)&Ks[s*128 + ty*8];
        float4 k1 = *(const float4*)&Ks[s*128 + ty*8 + 4];
        float4 v0 = *(const float4*)&Vs[s*128 + tx*8];
        float4 v1 = *(const float4*)&Vs[s*128 + tx*8 + 4];
        float kf[8] = {k0.x,k0.y,k0.z,k0.w,k1.x,k1.y,k1.z,k1.w};
        float vf[8] = {v0.x,v0.y,v0.z,v0.w,v1.x,v1.y,v1.z,v1.w};
        #pragma unroll
        for (int i = 0; i < 8; i++)
            #pragma unroll
            for (int j = 0; j < 8; j++) acc[i][j] += kf[i]*vf[j];
    }
    float* dst = g_kvp + bx*HH;
    #pragma unroll
    for (int i = 0; i < 8; i++) {
        #pragma unroll
        for (int j = 0; j < 2; j++) {
            float4 r = make_float4(acc[i][j*4], acc[i][j*4+1], acc[i][j*4+2], acc[i][j*4+3]);
            *(float4*)&dst[(ty*8+i)*128 + tx*8 + j*4] = r;
        }
    }
}

// ---------------- inter-chunk scan (resettable, sums quarters) ----------------
__global__ __launch_bounds__(128) void scan_kernel() {
    int e = blockIdx.x * 128 + threadIdx.x;   // 128 blocks x 128 threads = 16384
    float S = 0.f;
    #pragma unroll 4
    for (int c = 0; c < NC; c++) {
        float kv = g_kvp[(c*4+0)*HH + e] + g_kvp[(c*4+1)*HH + e]
                 + g_kvp[(c*4+2)*HH + e] + g_kvp[(c*4+3)*HH + e];
        g_S[c*HH + e] = S;
        S = (g_crst[c] ? 0.f : S) + kv;
    }
}

// ---------------- intra-chunk attention + residual ---------------------------
__global__ __launch_bounds__(256) void attn_kernel() {
    extern __shared__ float sm[];
    float* buf = sm;               // 128x128: Kt, then V, then S
    float* Qs  = sm + 128*128;     // [t][k] 32x128
    float* P   = Qs + 32*128;      // [t][s] 32x128
    __shared__ float den_s[32];
    __shared__ int rl_s[32];

    int bx = blockIdx.x;
    int c  = bx >> 2;
    int tb = (bx & 3) * 32;
    int cbase = c * C;
    int tid = threadIdx.x;
    int gt = tid >> 5, gs = tid & 31;

    if (tid < 32) rl_s[tid] = g_rloc[cbase + tb + tid];
    {
        const float4* Kt4 = (const float4*)(g_kT + c*HH);
        float4* buf4 = (float4*)buf;
        #pragma unroll
        for (int it = 0; it < 16; it++) buf4[tid + it*256] = Kt4[tid + it*256];
        const float4* Q4 = (const float4*)(g_q + (cbase + tb)*H);
        float4* Qs4 = (float4*)Qs;
        #pragma unroll
        for (int it = 0; it < 4; it++) Qs4[tid + it*256] = Q4[tid + it*256];
    }
    __syncthreads();

    // Stage A: P[t][s] = q_t . k_s   (buf = Kt[k][s])
    {
        float acc[4][4] = {};
        #pragma unroll 16
        for (int k = 0; k < 128; k++) {
            float4 kf = *(const float4*)&buf[k*128 + gs*4];
            #pragma unroll
            for (int i = 0; i < 4; i++) {
                float q = Qs[(gt*4+i)*128 + k];
                acc[i][0] += q*kf.x; acc[i][1] += q*kf.y;
                acc[i][2] += q*kf.z; acc[i][3] += q*kf.w;
            }
        }
        #pragma unroll
        for (int i = 0; i < 4; i++) {
            int t_idx = gt*4 + i;
            int tl = tb + t_idx;
            int rl = rl_s[t_idx];
            int lo = (rl < 0) ? 0 : rl;
            float pr[4];
            #pragma unroll
            for (int j = 0; j < 4; j++) {
                int s = gs*4 + j;
                float val = acc[i][j];
                if (s == tl) den_s[t_idx] = 1e-6f + val;
                pr[j] = (s >= lo && s <= tl) ? val : 0.f;
            }
            *(float4*)&P[t_idx*128 + gs*4] = make_float4(pr[0],pr[1],pr[2],pr[3]);
        }
    }
    __syncthreads();

    // load V into buf
    {
        const float4* V4 = (const float4*)(g_v + cbase*H);
        float4* buf4 = (float4*)buf;
        #pragma unroll
        for (int it = 0; it < 16; it++) buf4[tid + it*256] = V4[tid + it*256];
    }
    __syncthreads();

    float acc[4][4] = {};
    // B1: P @ V   (buf = V[s][v])
    #pragma unroll 16
    for (int s = 0; s < 128; s++) {
        float4 vf = *(const float4*)&buf[s*128 + gs*4];
        #pragma unroll
        for (int i = 0; i < 4; i++) {
            float p = P[(gt*4+i)*128 + s];
            acc[i][0] += p*vf.x; acc[i][1] += p*vf.y;
            acc[i][2] += p*vf.z; acc[i][3] += p*vf.w;
        }
    }
    __syncthreads();

    // load S into buf
    {
        const float4* S4 = (const float4*)(g_S + c*HH);
        float4* buf4 = (float4*)buf;
        #pragma unroll
        for (int it = 0; it < 16; it++) buf4[tid + it*256] = S4[tid + it*256];
    }
    __syncthreads();

    // B2: + gate * Q @ S   (buf = S[k][v])
    {
        float u[4];
        #pragma unroll
        for (int i = 0; i < 4; i++) u[i] = (rl_s[gt*4+i] < 0) ? 1.f : 0.f;
        #pragma unroll 16
        for (int k = 0; k < 128; k++) {
            float4 sf = *(const float4*)&buf[k*128 + gs*4];
            #pragma unroll
            for (int i = 0; i < 4; i++) {
                float q = Qs[(gt*4+i)*128 + k] * u[i];
                acc[i][0] += q*sf.x; acc[i][1] += q*sf.y;
                acc[i][2] += q*sf.z; acc[i][3] += q*sf.w;
            }
        }
    }

    // epilogue: z = num/den + x
    #pragma unroll
    for (int i = 0; i < 4; i++) {
        int t_idx = gt*4 + i;
        int tg = cbase + tb + t_idx;
        float d = 1.f / den_s[t_idx];
        float4 xr = *(const float4*)&g_x[tg*H + gs*4];
        float4 r;
        r.x = acc[i][0]*d + xr.x; r.y = acc[i][1]*d + xr.y;
        r.z = acc[i][2]*d + xr.z; r.w = acc[i][3]*d + xr.w;
        *(float4*)&g_z[tg*H + gs*4] = r;
    }
}

// ---------------- launch ------------------------------------------------------
extern "C" void kernel_launch(void* const* d_in, const int* in_sizes, int n_in,
                              void* d_out, int out_size) {
    const float* emb          = (const float*)d_in[0];
    const unsigned char* start= (const unsigned char*)d_in[1];
    const float* W_in         = (const float*)d_in[2];
    const float* b_in         = (const float*)d_in[3];
    const float* W_q          = (const float*)d_in[4];
    const float* W_k          = (const float*)d_in[5];
    const float* W_v          = (const float*)d_in[6];
    const float* W_ff         = (const float*)d_in[7];
    const float* b_ff         = (const float*)d_in[8];
    const float* W_out        = (const float*)d_in[9];
    const float* b_out        = (const float*)d_in[10];
    float* out = (float*)d_out;

    cudaFuncSetAttribute(gemm32<0>, cudaFuncAttributeMaxDynamicSharedMemorySize, SMG);
    cudaFuncSetAttribute(gemm32<2>, cudaFuncAttributeMaxDynamicSharedMemorySize, SMG);
    cudaFuncSetAttribute(qkv_kernel, cudaFuncAttributeMaxDynamicSharedMemorySize, SMG);
    cudaFuncSetAttribute(attn_kernel, cudaFuncAttributeMaxDynamicSharedMemorySize, SMA);

    float *px, *pz, *pWt;
    cudaGetSymbolAddress((void**)&px, g_x);
    cudaGetSymbolAddress((void**)&pz, g_z);
    cudaGetSymbolAddress((void**)&pWt, g_Wt);

    reset_kernel<<<NC, C>>>(start);
    wt_kernel<<<dim3(4,4,10), dim3(32,8)>>>(W_in, W_q, W_k, W_v, W_ff, W_out);
    gemm32<0><<<T/32, 256, SMG>>>(emb, pWt, b_in, px);

    for (int l = 0; l < L; l++) {
        qkv_kernel<<<dim3(T/32, 3), 256, SMG>>>(px, pWt + (1+3*l)*HH,
                                                pWt + (2+3*l)*HH, pWt + (3+3*l)*HH);
        chunk_kv_kernel<<<NC*4, 256>>>();
        scan_kernel<<<128, 128>>>();
        attn_kernel<<<NC*4, 256, SMA>>>();
        gemm32<2><<<T/32, 256, SMG>>>(pz, pWt + (7+l)*HH, b_ff + l*H, px);
    }
    gemm32<0><<<T/32, 256, SMG>>>(px, pWt + 9*HH, b_out, out);
}

// round 4
// speedup vs baseline: 2.4300x; 1.0775x over previous
#include <cuda_runtime.h>
#include <math.h>

#define T 4096
#define H 128
#define HH (H*H)
#define C 128
#define NC (T/C)   // 32
#define L 2

// ---------------- scratch (device globals; no allocation allowed) ------------
__device__ float g_x[T*H];
__device__ float g_q[T*H];
__device__ float g_k[T*H];
__device__ float g_kT[T*H];      // per-chunk transposed K: [c][k][s_local]
__device__ float g_v[T*H];
__device__ float g_Wt[10*HH];    // transposed weights [k][n]
__device__ float g_kvp[4*NC*HH]; // per-(chunk,quarter) KV partial sums
__device__ float g_S[NC*HH];     // state before each chunk
__device__ int   g_rloc[T];      // last reset index within chunk (local), -1 if none
__device__ int   g_cs0[NC];      // chunk tail-sum start (local)
__device__ int   g_crst[NC];     // chunk has reset flag

#define SMG ((128*128 + 32*128)*4)              // qkv: W + A tile
#define SMA ((128*128 + 32*128 + 32*128)*4)     // attn: buf + Q + P

// ---------------- prep: weight transpose + reset preprocessing ---------------
__global__ void prep_kernel(const float* __restrict__ W_in, const float* __restrict__ W_q,
                            const float* __restrict__ W_k, const float* __restrict__ W_v,
                            const float* __restrict__ W_ff, const float* __restrict__ W_out,
                            const unsigned char* __restrict__ start) {
    int b = blockIdx.x;
    int tid = threadIdx.x;
    if (b < 160) {
        __shared__ float tile[32][33];
        int z = b >> 4, sub = b & 15;
        const float* src;
        switch (z) {
            case 0: src = W_in; break;
            case 1: src = W_q; break;
            case 2: src = W_k; break;
            case 3: src = W_v; break;
            case 4: src = W_q + HH; break;
            case 5: src = W_k + HH; break;
            case 6: src = W_v + HH; break;
            case 7: src = W_ff; break;
            case 8: src = W_ff + HH; break;
            default: src = W_out; break;
        }
        float* dst = g_Wt + z*HH;
        int k0 = (sub >> 2)*32, n0 = (sub & 3)*32;
        int tx = tid & 31, ty = tid >> 5;    // (32,8)
        #pragma unroll
        for (int i = 0; i < 4; i++)
            tile[ty + 8*i][tx] = src[(n0 + ty + 8*i)*H + k0 + tx];
        __syncthreads();
        #pragma unroll
        for (int i = 0; i < 4; i++)
            dst[(k0 + ty + 8*i)*H + n0 + tx] = tile[tx][ty + 8*i];
    } else {
        __shared__ unsigned char f[C];
        int c = b - 160;
        if (tid < C) f[tid] = start[c*C + tid];
        __syncthreads();
        if (tid < C) {
            int r = -1;
            for (int j = tid; j >= 0; --j) { if (f[j]) { r = j; break; } }
            g_rloc[c*C + tid] = r;
            if (tid == C-1) { g_cs0[c] = (r >= 0) ? r : 0; g_crst[c] = (r >= 0) ? 1 : 0; }
        }
    }
}

// ---------------- shared GEMM microkernel ------------------------------------
__device__ __forceinline__ void ldW(float* Ws, const float* __restrict__ Wt, int tid) {
    const float4* Wt4 = (const float4*)Wt;
    float4* Ws4 = (float4*)Ws;
    #pragma unroll
    for (int it = 0; it < 16; it++) Ws4[tid + it*256] = Wt4[tid + it*256];
}

__device__ __forceinline__ void mm32(float acc[4][4], const float* As, const float* Ws,
                                     int gt, int gs) {
    #pragma unroll
    for (int i = 0; i < 4; i++)
        #pragma unroll
        for (int j = 0; j < 4; j++) acc[i][j] = 0.f;
    #pragma unroll 16
    for (int k = 0; k < 128; k++) {
        float4 w = *(const float4*)&Ws[k*128 + gs*4];
        #pragma unroll
        for (int i = 0; i < 4; i++) {
            float a = As[(gt*4+i)*128 + k];
            acc[i][0] += a*w.x; acc[i][1] += a*w.y;
            acc[i][2] += a*w.z; acc[i][3] += a*w.w;
        }
    }
}

__device__ __forceinline__ float phi_f(float v) {
    return (v > 0.f) ? (1.f + v) : __expf(v);
}

// ---------------- fused [map_in] + QKV ---------------------------------------
template<int FIRST>
__global__ __launch_bounds__(256) void qkv_kernel(const float* __restrict__ A0,
        const float* __restrict__ Wt_in, const float* __restrict__ b_in,
        const float* __restrict__ Wtq, const float* __restrict__ Wtk,
        const float* __restrict__ Wtv) {
    extern __shared__ float sm[];
    float* Ws = sm;               // [k][n] 128x128
    float* As = sm + HH;          // [r][k] 32x128
    int tid = threadIdx.x;
    int t0 = blockIdx.x * 32;
    int gt = tid >> 5, gs = tid & 31;

    {   // load activation tile + first weight
        const float4* A4 = (const float4*)(A0 + t0*H);
        float4* As4 = (float4*)As;
        #pragma unroll
        for (int it = 0; it < 4; it++) As4[tid + it*256] = A4[tid + it*256];
        ldW(Ws, FIRST ? Wt_in : Wtq, tid);
    }
    __syncthreads();

    if (FIRST) {   // x = emb @ W_in^T + b_in, keep in As, write g_x
        float acc[4][4];
        mm32(acc, As, Ws, gt, gs);
        __syncthreads();
        float4 bb = *(const float4*)&b_in[gs*4];
        #pragma unroll
        for (int i = 0; i < 4; i++) {
            float4 r = make_float4(acc[i][0]+bb.x, acc[i][1]+bb.y,
                                   acc[i][2]+bb.z, acc[i][3]+bb.w);
            *(float4*)&As[(gt*4+i)*128 + gs*4] = r;
            *(float4*)&g_x[(t0 + gt*4+i)*H + gs*4] = r;
        }
        ldW(Ws, Wtq, tid);
        __syncthreads();
    }

    {   // q = phi(x @ Wq^T)
        float acc[4][4];
        mm32(acc, As, Ws, gt, gs);
        #pragma unroll
        for (int i = 0; i < 4; i++) {
            float4 r = make_float4(phi_f(acc[i][0]), phi_f(acc[i][1]),
                                   phi_f(acc[i][2]), phi_f(acc[i][3]));
            *(float4*)&g_q[(t0 + gt*4+i)*H + gs*4] = r;
        }
        __syncthreads();
        ldW(Ws, Wtk, tid);
        __syncthreads();
    }
    {   // k = phi(x @ Wk^T) (+ transposed copy)
        float acc[4][4];
        mm32(acc, As, Ws, gt, gs);
        #pragma unroll
        for (int i = 0; i < 4; i++) {
            int t = t0 + gt*4 + i;
            float r[4] = {phi_f(acc[i][0]), phi_f(acc[i][1]),
                          phi_f(acc[i][2]), phi_f(acc[i][3])};
            *(float4*)&g_k[t*H + gs*4] = make_float4(r[0],r[1],r[2],r[3]);
            int c = t >> 7, sl = t & 127;
            float* kT = g_kT + c*HH + sl;
            #pragma unroll
            for (int j = 0; j < 4; j++) kT[(gs*4+j)*128] = r[j];
        }
        __syncthreads();
        ldW(Ws, Wtv, tid);
        __syncthreads();
    }
    {   // v = x @ Wv^T
        float acc[4][4];
        mm32(acc, As, Ws, gt, gs);
        #pragma unroll
        for (int i = 0; i < 4; i++)
            *(float4*)&g_v[(t0 + gt*4+i)*H + gs*4] =
                make_float4(acc[i][0], acc[i][1], acc[i][2], acc[i][3]);
    }
}

// ---------------- per-chunk-quarter KV partials: g_kvp = K_q^T @ V_q ---------
__global__ __launch_bounds__(256) void chunk_kv_kernel() {
    __shared__ float Ks[32*128];
    __shared__ float Vs[32*128];
    int bx = blockIdx.x;
    int c = bx >> 2, qi = bx & 3;
    int s0 = g_cs0[c];
    int tid = threadIdx.x;
    int base = (c*C + qi*32) * H;
    {
        const float4* K4 = (const float4*)(g_k + base);
        const float4* V4 = (const float4*)(g_v + base);
        float4* Ks4 = (float4*)Ks;
        float4* Vs4 = (float4*)Vs;
        #pragma unroll
        for (int it = 0; it < 4; it++) {
            int idx = tid + it*256;
            int srow = idx >> 5;
            float4 kv4 = K4[idx];
            if (qi*32 + srow < s0) kv4 = make_float4(0.f,0.f,0.f,0.f);
            Ks4[idx] = kv4;
            Vs4[idx] = V4[idx];
        }
    }
    __syncthreads();
    int ty = tid >> 4, tx = tid & 15;
    float acc[8][8] = {};
    #pragma unroll 4
    for (int s = 0; s < 32; s++) {
        float4 k0 = *(const float4*)&Ks[s*128 + ty*8];
        float4 k1 = *(const float4*)&Ks[s*128 + ty*8 + 4];
        float4 v0 = *(const float4*)&Vs[s*128 + tx*8];
        float4 v1 = *(const float4*)&Vs[s*128 + tx*8 + 4];
        float kf[8] = {k0.x,k0.y,k0.z,k0.w,k1.x,k1.y,k1.z,k1.w};
        float vf[8] = {v0.x,v0.y,v0.z,v0.w,v1.x,v1.y,v1.z,v1.w};
        #pragma unroll
        for (int i = 0; i < 8; i++)
            #pragma unroll
            for (int j = 0; j < 8; j++) acc[i][j] += kf[i]*vf[j];
    }
    float* dst = g_kvp + bx*HH;
    #pragma unroll
    for (int i = 0; i < 8; i++)
        #pragma unroll
        for (int j = 0; j < 2; j++)
            *(float4*)&dst[(ty*8+i)*128 + tx*8 + j*4] =
                make_float4(acc[i][j*4], acc[i][j*4+1], acc[i][j*4+2], acc[i][j*4+3]);
}

// ---------------- inter-chunk scan (resettable, sums quarters) ----------------
__global__ __launch_bounds__(128) void scan_kernel() {
    int e = blockIdx.x * 128 + threadIdx.x;
    float S = 0.f;
    #pragma unroll 4
    for (int c = 0; c < NC; c++) {
        float kv = g_kvp[(c*4+0)*HH + e] + g_kvp[(c*4+1)*HH + e]
                 + g_kvp[(c*4+2)*HH + e] + g_kvp[(c*4+3)*HH + e];
        g_S[c*HH + e] = S;
        S = (g_crst[c] ? 0.f : S) + kv;
    }
}

// ---------------- fused attn + FF [+ map_out] --------------------------------
template<int LAST>
__global__ __launch_bounds__(256) void attn_ff_kernel(
        const float* __restrict__ Wff, const float* __restrict__ bff,
        const float* __restrict__ Wout, const float* __restrict__ bout,
        float* __restrict__ outp) {
    extern __shared__ float sm[];
    float* buf = sm;               // 128x128: Kt -> V -> S -> Wff -> Wout
    float* Qs  = sm + HH;          // [t][k] 32x128  (later: x tile)
    float* P   = Qs + 32*128;      // [t][s] 32x128  (later: z tile)
    __shared__ float den_s[32];
    __shared__ int rl_s[32];

    int bx = blockIdx.x;
    int c  = bx >> 2;
    int tb = (bx & 3) * 32;
    int cbase = c * C;
    int tid = threadIdx.x;
    int gt = tid >> 5, gs = tid & 31;

    if (tid < 32) rl_s[tid] = g_rloc[cbase + tb + tid];
    {
        const float4* Kt4 = (const float4*)(g_kT + c*HH);
        float4* buf4 = (float4*)buf;
        #pragma unroll
        for (int it = 0; it < 16; it++) buf4[tid + it*256] = Kt4[tid + it*256];
        const float4* Q4 = (const float4*)(g_q + (cbase + tb)*H);
        float4* Qs4 = (float4*)Qs;
        #pragma unroll
        for (int it = 0; it < 4; it++) Qs4[tid + it*256] = Q4[tid + it*256];
    }
    __syncthreads();

    // Stage A: P[t][s] = q_t . k_s
    {
        float acc[4][4];
        mm32(acc, Qs, buf, gt, gs);
        #pragma unroll
        for (int i = 0; i < 4; i++) {
            int t_idx = gt*4 + i;
            int tl = tb + t_idx;
            int rl = rl_s[t_idx];
            int lo = (rl < 0) ? 0 : rl;
            float pr[4];
            #pragma unroll
            for (int j = 0; j < 4; j++) {
                int s = gs*4 + j;
                float val = acc[i][j];
                if (s == tl) den_s[t_idx] = 1e-6f + val;
                pr[j] = (s >= lo && s <= tl) ? val : 0.f;
            }
            *(float4*)&P[t_idx*128 + gs*4] = make_float4(pr[0],pr[1],pr[2],pr[3]);
        }
    }
    __syncthreads();
    {   // buf <- V
        const float4* V4 = (const float4*)(g_v + cbase*H);
        float4* buf4 = (float4*)buf;
        #pragma unroll
        for (int it = 0; it < 16; it++) buf4[tid + it*256] = V4[tid + it*256];
    }
    __syncthreads();

    float acc[4][4] = {};
    #pragma unroll 16
    for (int s = 0; s < 128; s++) {   // B1: P @ V
        float4 vf = *(const float4*)&buf[s*128 + gs*4];
        #pragma unroll
        for (int i = 0; i < 4; i++) {
            float p = P[(gt*4+i)*128 + s];
            acc[i][0] += p*vf.x; acc[i][1] += p*vf.y;
            acc[i][2] += p*vf.z; acc[i][3] += p*vf.w;
        }
    }
    __syncthreads();
    {   // buf <- S
        const float4* S4 = (const float4*)(g_S + c*HH);
        float4* buf4 = (float4*)buf;
        #pragma unroll
        for (int it = 0; it < 16; it++) buf4[tid + it*256] = S4[tid + it*256];
    }
    __syncthreads();
    {   // B2: + gate * Q @ S
        float u[4];
        #pragma unroll
        for (int i = 0; i < 4; i++) u[i] = (rl_s[gt*4+i] < 0) ? 1.f : 0.f;
        #pragma unroll 16
        for (int k = 0; k < 128; k++) {
            float4 sf = *(const float4*)&buf[k*128 + gs*4];
            #pragma unroll
            for (int i = 0; i < 4; i++) {
                float q = Qs[(gt*4+i)*128 + k] * u[i];
                acc[i][0] += q*sf.x; acc[i][1] += q*sf.y;
                acc[i][2] += q*sf.z; acc[i][3] += q*sf.w;
            }
        }
    }

    // z = num/den + x  -> store into P (z tile)
    #pragma unroll
    for (int i = 0; i < 4; i++) {
        int t_idx = gt*4 + i;
        int tg = cbase + tb + t_idx;
        float d = 1.f / den_s[t_idx];
        float4 xr = *(const float4*)&g_x[tg*H + gs*4];
        float4 r;
        r.x = acc[i][0]*d + xr.x; r.y = acc[i][1]*d + xr.y;
        r.z = acc[i][2]*d + xr.z; r.w = acc[i][3]*d + xr.w;
        *(float4*)&P[t_idx*128 + gs*4] = r;
    }
    __syncthreads();
    ldW(buf, Wff, tid);   // buf <- Wff
    __syncthreads();

    {   // FF: x = leaky(z @ Wff^T + bff)
        float fa[4][4];
        mm32(fa, P, buf, gt, gs);
        float4 bb = *(const float4*)&bff[gs*4];
        #pragma unroll
        for (int i = 0; i < 4; i++) {
            int tg = cbase + tb + gt*4 + i;
            float r[4] = {fa[i][0]+bb.x, fa[i][1]+bb.y, fa[i][2]+bb.z, fa[i][3]+bb.w};
            #pragma unroll
            for (int j = 0; j < 4; j++) r[j] = (r[j] > 0.f) ? r[j] : 0.01f*r[j];
            float4 rr = make_float4(r[0],r[1],r[2],r[3]);
            *(float4*)&g_x[tg*H + gs*4] = rr;
            if (LAST) *(float4*)&Qs[(gt*4+i)*128 + gs*4] = rr;
        }
    }
    if (LAST) {
        __syncthreads();
        ldW(buf, Wout, tid);   // buf <- Wout
        __syncthreads();
        float fa[4][4];
        mm32(fa, Qs, buf, gt, gs);
        float4 bb = *(const float4*)&bout[gs*4];
        #pragma unroll
        for (int i = 0; i < 4; i++) {
            int tg = cbase + tb + gt*4 + i;
            *(float4*)&outp[tg*H + gs*4] =
                make_float4(fa[i][0]+bb.x, fa[i][1]+bb.y, fa[i][2]+bb.z, fa[i][3]+bb.w);
        }
    }
}

// ---------------- launch ------------------------------------------------------
extern "C" void kernel_launch(void* const* d_in, const int* in_sizes, int n_in,
                              void* d_out, int out_size) {
    const float* emb          = (const float*)d_in[0];
    const unsigned char* start= (const unsigned char*)d_in[1];
    const float* W_in         = (const float*)d_in[2];
    const float* b_in         = (const float*)d_in[3];
    const float* W_q          = (const float*)d_in[4];
    const float* W_k          = (const float*)d_in[5];
    const float* W_v          = (const float*)d_in[6];
    const float* W_ff         = (const float*)d_in[7];
    const float* b_ff         = (const float*)d_in[8];
    const float* W_out        = (const float*)d_in[9];
    const float* b_out        = (const float*)d_in[10];
    float* out = (float*)d_out;

    cudaFuncSetAttribute(qkv_kernel<1>, cudaFuncAttributeMaxDynamicSharedMemorySize, SMG);
    cudaFuncSetAttribute(qkv_kernel<0>, cudaFuncAttributeMaxDynamicSharedMemorySize, SMG);
    cudaFuncSetAttribute(attn_ff_kernel<0>, cudaFuncAttributeMaxDynamicSharedMemorySize, SMA);
    cudaFuncSetAttribute(attn_ff_kernel<1>, cudaFuncAttributeMaxDynamicSharedMemorySize, SMA);

    float *px, *pWt;
    cudaGetSymbolAddress((void**)&px, g_x);
    cudaGetSymbolAddress((void**)&pWt, g_Wt);

    prep_kernel<<<192, 256>>>(W_in, W_q, W_k, W_v, W_ff, W_out, start);

    // layer 0 (fused map_in)
    qkv_kernel<1><<<T/32, 256, SMG>>>(emb, pWt, b_in,
                                      pWt + 1*HH, pWt + 2*HH, pWt + 3*HH);
    chunk_kv_kernel<<<NC*4, 256>>>();
    scan_kernel<<<128, 128>>>();
    attn_ff_kernel<0><<<NC*4, 256, SMA>>>(pWt + 7*HH, b_ff, nullptr, nullptr, nullptr);

    // layer 1 (fused map_out)
    qkv_kernel<0><<<T/32, 256, SMG>>>(px, nullptr, nullptr,
                                      pWt + 4*HH, pWt + 5*HH, pWt + 6*HH);
    chunk_kv_kernel<<<NC*4, 256>>>();
    scan_kernel<<<128, 128>>>();
    attn_ff_kernel<1><<<NC*4, 256, SMA>>>(pWt + 8*HH, b_ff + H,
                                          pWt + 9*HH, b_out, out);
}

// round 5
// speedup vs baseline: 2.9815x; 1.2270x over previous
#include <cuda_runtime.h>
#include <cuda_pipeline.h>
#include <math.h>

#define T 4096
#define H 128
#define HH (H*H)
#define C 128
#define NC (T/C)   // 32
#define L 2

// ---------------- scratch (device globals; no allocation allowed) ------------
__device__ float g_x[T*H];
__device__ float g_q[T*H];
__device__ float g_k[T*H];
__device__ float g_kT[T*H];      // per-chunk transposed K: [c][k][s_local]
__device__ float g_v[T*H];
__device__ float g_Wt[10*HH];    // transposed weights [k][n]
__device__ float g_kvp[4*NC*HH]; // per-(chunk,quarter) KV partial sums
__device__ float g_S[NC*HH];     // state before each chunk
__device__ int   g_rloc[T];      // last reset index within chunk (local), -1 if none
__device__ int   g_cs0[NC];      // chunk tail-sum start (local)
__device__ int   g_crst[NC];     // chunk has reset flag

#define SMG ((2*HH + 32*128)*4)             // qkv: W0 + W1 + A tile   (144KB)
#define SMA ((2*HH + 2*32*128)*4)           // attn: bufA + bufB + Q + P (160KB)

// ---------------- prep: weight transpose + reset preprocessing ---------------
__global__ void prep_kernel(const float* __restrict__ W_in, const float* __restrict__ W_q,
                            const float* __restrict__ W_k, const float* __restrict__ W_v,
                            const float* __restrict__ W_ff, const float* __restrict__ W_out,
                            const unsigned char* __restrict__ start) {
    int b = blockIdx.x;
    int tid = threadIdx.x;
    if (b < 160) {
        __shared__ float tile[32][33];
        int z = b >> 4, sub = b & 15;
        const float* src;
        switch (z) {
            case 0: src = W_in; break;
            case 1: src = W_q; break;
            case 2: src = W_k; break;
            case 3: src = W_v; break;
            case 4: src = W_q + HH; break;
            case 5: src = W_k + HH; break;
            case 6: src = W_v + HH; break;
            case 7: src = W_ff; break;
            case 8: src = W_ff + HH; break;
            default: src = W_out; break;
        }
        float* dst = g_Wt + z*HH;
        int k0 = (sub >> 2)*32, n0 = (sub & 3)*32;
        int tx = tid & 31, ty = tid >> 5;    // (32,8)
        #pragma unroll
        for (int i = 0; i < 4; i++)
            tile[ty + 8*i][tx] = src[(n0 + ty + 8*i)*H + k0 + tx];
        __syncthreads();
        #pragma unroll
        for (int i = 0; i < 4; i++)
            dst[(k0 + ty + 8*i)*H + n0 + tx] = tile[tx][ty + 8*i];
    } else {
        __shared__ unsigned char f[C];
        int c = b - 160;
        if (tid < C) f[tid] = start[c*C + tid];
        __syncthreads();
        if (tid < C) {
            int r = -1;
            for (int j = tid; j >= 0; --j) { if (f[j]) { r = j; break; } }
            g_rloc[c*C + tid] = r;
            if (tid == C-1) { g_cs0[c] = (r >= 0) ? r : 0; g_crst[c] = (r >= 0) ? 1 : 0; }
        }
    }
}

// ---------------- async-copy helpers -----------------------------------------
__device__ __forceinline__ void cpW(float* Ws, const float* __restrict__ Wt, int tid) {
    #pragma unroll
    for (int it = 0; it < 16; it++) {
        int idx = (tid + it*256) * 4;
        __pipeline_memcpy_async(Ws + idx, Wt + idx, 16);
    }
}
__device__ __forceinline__ void cpA(float* As, const float* __restrict__ A, int tid) {
    #pragma unroll
    for (int it = 0; it < 4; it++) {
        int idx = (tid + it*256) * 4;
        __pipeline_memcpy_async(As + idx, A + idx, 16);
    }
}

// ---------------- shared GEMM microkernel ------------------------------------
__device__ __forceinline__ void mm32(float acc[4][4], const float* As, const float* Ws,
                                     int gt, int gs) {
    #pragma unroll
    for (int i = 0; i < 4; i++)
        #pragma unroll
        for (int j = 0; j < 4; j++) acc[i][j] = 0.f;
    #pragma unroll 16
    for (int k = 0; k < 128; k++) {
        float4 w = *(const float4*)&Ws[k*128 + gs*4];
        #pragma unroll
        for (int i = 0; i < 4; i++) {
            float a = As[(gt*4+i)*128 + k];
            acc[i][0] += a*w.x; acc[i][1] += a*w.y;
            acc[i][2] += a*w.z; acc[i][3] += a*w.w;
        }
    }
}

__device__ __forceinline__ float phi_f(float v) {
    return (v > 0.f) ? (1.f + v) : __expf(v);
}

// ---------------- fused [map_in] + QKV (cp.async double-buffered W) ----------
template<int FIRST>
__global__ __launch_bounds__(256) void qkv_kernel(const float* __restrict__ A0,
        const float* __restrict__ Wt_in, const float* __restrict__ b_in,
        const float* __restrict__ Wtq, const float* __restrict__ Wtk,
        const float* __restrict__ Wtv) {
    extern __shared__ float sm[];
    float* W0 = sm;               // [k][n] 128x128
    float* W1 = sm + HH;
    float* As = sm + 2*HH;        // [r][k] 32x128
    int tid = threadIdx.x;
    int t0 = blockIdx.x * 32;
    int gt = tid >> 5, gs = tid & 31;

    cpA(As, A0 + t0*H, tid);
    cpW(W0, FIRST ? Wt_in : Wtq, tid);
    __pipeline_commit();                       // g0: A + first W
    cpW(W1, FIRST ? Wtq : Wtk, tid);
    __pipeline_commit();                       // g1
    __pipeline_wait_prior(1);
    __syncthreads();

    if (FIRST) {   // x = emb @ W_in^T + b_in  (keep in As, write g_x)
        float acc[4][4];
        mm32(acc, As, W0, gt, gs);
        __syncthreads();                       // all reads of As/W0 done
        cpW(W0, Wtk, tid);
        __pipeline_commit();                   // g2: Wk -> W0
        float4 bb = *(const float4*)&b_in[gs*4];
        #pragma unroll
        for (int i = 0; i < 4; i++) {
            float4 r = make_float4(acc[i][0]+bb.x, acc[i][1]+bb.y,
                                   acc[i][2]+bb.z, acc[i][3]+bb.w);
            *(float4*)&As[(gt*4+i)*128 + gs*4] = r;
            *(float4*)&g_x[(t0 + gt*4+i)*H + gs*4] = r;
        }
        __pipeline_wait_prior(1);              // g1 (Wq in W1) done
        __syncthreads();
        {   // q = phi(x @ Wq^T)   [W1]
            float acc2[4][4];
            mm32(acc2, As, W1, gt, gs);
            #pragma unroll
            for (int i = 0; i < 4; i++)
                *(float4*)&g_q[(t0 + gt*4+i)*H + gs*4] =
                    make_float4(phi_f(acc2[i][0]), phi_f(acc2[i][1]),
                                phi_f(acc2[i][2]), phi_f(acc2[i][3]));
        }
        __syncthreads();                       // W1 free
        cpW(W1, Wtv, tid);
        __pipeline_commit();                   // g3: Wv -> W1
        __pipeline_wait_prior(1);              // g2 (Wk in W0) done
        __syncthreads();
        {   // k = phi(x @ Wk^T)   [W0]
            float acc2[4][4];
            mm32(acc2, As, W0, gt, gs);
            #pragma unroll
            for (int i = 0; i < 4; i++) {
                int t = t0 + gt*4 + i;
                float r[4] = {phi_f(acc2[i][0]), phi_f(acc2[i][1]),
                              phi_f(acc2[i][2]), phi_f(acc2[i][3])};
                *(float4*)&g_k[t*H + gs*4] = make_float4(r[0],r[1],r[2],r[3]);
                int cc = t >> 7, sl = t & 127;
                float* kT = g_kT + cc*HH + sl;
                #pragma unroll
                for (int j = 0; j < 4; j++) kT[(gs*4+j)*128] = r[j];
            }
        }
        __pipeline_wait_prior(0);              // g3 (Wv in W1) done
        __syncthreads();
        {   // v = x @ Wv^T        [W1]
            float acc2[4][4];
            mm32(acc2, As, W1, gt, gs);
            #pragma unroll
            for (int i = 0; i < 4; i++)
                *(float4*)&g_v[(t0 + gt*4+i)*H + gs*4] =
                    make_float4(acc2[i][0], acc2[i][1], acc2[i][2], acc2[i][3]);
        }
    } else {
        {   // q = phi(x @ Wq^T)   [W0]
            float acc[4][4];
            mm32(acc, As, W0, gt, gs);
            #pragma unroll
            for (int i = 0; i < 4; i++)
                *(float4*)&g_q[(t0 + gt*4+i)*H + gs*4] =
                    make_float4(phi_f(acc[i][0]), phi_f(acc[i][1]),
                                phi_f(acc[i][2]), phi_f(acc[i][3]));
        }
        __syncthreads();                       // W0 free
        cpW(W0, Wtv, tid);
        __pipeline_commit();                   // g2: Wv -> W0
        __pipeline_wait_prior(1);              // g1 (Wk in W1) done
        __syncthreads();
        {   // k = phi(x @ Wk^T)   [W1]
            float acc[4][4];
            mm32(acc, As, W1, gt, gs);
            #pragma unroll
            for (int i = 0; i < 4; i++) {
                int t = t0 + gt*4 + i;
                float r[4] = {phi_f(acc[i][0]), phi_f(acc[i][1]),
                              phi_f(acc[i][2]), phi_f(acc[i][3])};
                *(float4*)&g_k[t*H + gs*4] = make_float4(r[0],r[1],r[2],r[3]);
                int cc = t >> 7, sl = t & 127;
                float* kT = g_kT + cc*HH + sl;
                #pragma unroll
                for (int j = 0; j < 4; j++) kT[(gs*4+j)*128] = r[j];
            }
        }
        __pipeline_wait_prior(0);              // g2 (Wv in W0) done
        __syncthreads();
        {   // v = x @ Wv^T        [W0]
            float acc[4][4];
            mm32(acc, As, W0, gt, gs);
            #pragma unroll
            for (int i = 0; i < 4; i++)
                *(float4*)&g_v[(t0 + gt*4+i)*H + gs*4] =
                    make_float4(acc[i][0], acc[i][1], acc[i][2], acc[i][3]);
        }
    }
}

// ---------------- per-chunk-quarter KV partials: g_kvp = K_q^T @ V_q ---------
__global__ __launch_bounds__(256) void chunk_kv_kernel() {
    __shared__ float Ks[32*128];
    __shared__ float Vs[32*128];
    int bx = blockIdx.x;
    int c = bx >> 2, qi = bx & 3;
    int s0 = g_cs0[c];
    int tid = threadIdx.x;
    int base = (c*C + qi*32) * H;
    {
        const float4* K4 = (const float4*)(g_k + base);
        const float4* V4 = (const float4*)(g_v + base);
        float4* Ks4 = (float4*)Ks;
        float4* Vs4 = (float4*)Vs;
        #pragma unroll
        for (int it = 0; it < 4; it++) {
            int idx = tid + it*256;
            int srow = idx >> 5;
            float4 kv4 = K4[idx];
            if (qi*32 + srow < s0) kv4 = make_float4(0.f,0.f,0.f,0.f);
            Ks4[idx] = kv4;
            Vs4[idx] = V4[idx];
        }
    }
    __syncthreads();
    int ty = tid >> 4, tx = tid & 15;
    float acc[8][8] = {};
    #pragma unroll 4
    for (int s = 0; s < 32; s++) {
        float4 k0 = *(const float4*)&Ks[s*128 + ty*8];
        float4 k1 = *(const float4*)&Ks[s*128 + ty*8 + 4];
        float4 v0 = *(const float4*)&Vs[s*128 + tx*8];
        float4 v1 = *(const float4*)&Vs[s*128 + tx*8 + 4];
        float kf[8] = {k0.x,k0.y,k0.z,k0.w,k1.x,k1.y,k1.z,k1.w};
        float vf[8] = {v0.x,v0.y,v0.z,v0.w,v1.x,v1.y,v1.z,v1.w};
        #pragma unroll
        for (int i = 0; i < 8; i++)
            #pragma unroll
            for (int j = 0; j < 8; j++) acc[i][j] += kf[i]*vf[j];
    }
    float* dst = g_kvp + bx*HH;
    #pragma unroll
    for (int i = 0; i < 8; i++)
        #pragma unroll
        for (int j = 0; j < 2; j++)
            *(float4*)&dst[(ty*8+i)*128 + tx*8 + j*4] =
                make_float4(acc[i][j*4], acc[i][j*4+1], acc[i][j*4+2], acc[i][j*4+3]);
}

// ---------------- inter-chunk scan (batched loads, MLP=16) --------------------
__global__ __launch_bounds__(128) void scan_kernel() {
    __shared__ int sc[NC];
    int tid = threadIdx.x;
    int e = blockIdx.x * 128 + tid;
    if (tid < NC) sc[tid] = g_crst[tid];
    __syncthreads();
    float S = 0.f;
    #pragma unroll
    for (int g = 0; g < 8; g++) {        // groups of 4 chunks, 16 loads in flight
        float v[4][4];
        #pragma unroll
        for (int cc = 0; cc < 4; cc++)
            #pragma unroll
            for (int q = 0; q < 4; q++)
                v[cc][q] = g_kvp[(((g*4 + cc)*4) + q)*HH + e];
        #pragma unroll
        for (int cc = 0; cc < 4; cc++) {
            int c = g*4 + cc;
            g_S[c*HH + e] = S;
            float kv = (v[cc][0] + v[cc][1]) + (v[cc][2] + v[cc][3]);
            S = sc[c] ? kv : S + kv;
        }
    }
}

// ---------------- fused attn + FF [+ map_out] (double-buffered) ---------------
template<int LAST>
__global__ __launch_bounds__(256) void attn_ff_kernel(
        const float* __restrict__ Wff, const float* __restrict__ bff,
        const float* __restrict__ Wout, const float* __restrict__ bout,
        float* __restrict__ outp) {
    extern __shared__ float sm[];
    float* bufA = sm;              // 128x128: Kt -> S -> Wout
    float* bufB = sm + HH;         // 128x128: V -> Wff
    float* Qs   = sm + 2*HH;       // [t][k] 32x128
    float* P    = Qs + 32*128;     // [t][s] 32x128 (later z tile)
    __shared__ float den_s[32];
    __shared__ int rl_s[32];

    int bx = blockIdx.x;
    int c  = bx >> 2;
    int tb = (bx & 3) * 32;
    int cbase = c * C;
    int tid = threadIdx.x;
    int gt = tid >> 5, gs = tid & 31;

    if (tid < 32) rl_s[tid] = g_rloc[cbase + tb + tid];
    cpW(bufA, g_kT + c*HH, tid);
    cpA(Qs, g_q + (cbase + tb)*H, tid);
    __pipeline_commit();                       // g0: Kt + Q
    cpW(bufB, g_v + cbase*H, tid);
    __pipeline_commit();                       // g1: V
    __pipeline_wait_prior(1);
    __syncthreads();

    // Stage A: P[t][s] = q_t . k_s   [bufA = Kt]
    {
        float acc[4][4];
        mm32(acc, Qs, bufA, gt, gs);
        #pragma unroll
        for (int i = 0; i < 4; i++) {
            int t_idx = gt*4 + i;
            int tl = tb + t_idx;
            int rl = rl_s[t_idx];
            int lo = (rl < 0) ? 0 : rl;
            float pr[4];
            #pragma unroll
            for (int j = 0; j < 4; j++) {
                int s = gs*4 + j;
                float val = acc[i][j];
                if (s == tl) den_s[t_idx] = 1e-6f + val;
                pr[j] = (s >= lo && s <= tl) ? val : 0.f;
            }
            *(float4*)&P[t_idx*128 + gs*4] = make_float4(pr[0],pr[1],pr[2],pr[3]);
        }
    }
    __syncthreads();                           // bufA free, P published
    cpW(bufA, g_S + c*HH, tid);
    __pipeline_commit();                       // g2: S -> bufA
    __pipeline_wait_prior(1);                  // g1 (V) done
    __syncthreads();

    float acc[4][4] = {};
    #pragma unroll 16
    for (int s = 0; s < 128; s++) {            // B1: P @ V   [bufB]
        float4 vf = *(const float4*)&bufB[s*128 + gs*4];
        #pragma unroll
        for (int i = 0; i < 4; i++) {
            float p = P[(gt*4+i)*128 + s];
            acc[i][0] += p*vf.x; acc[i][1] += p*vf.y;
            acc[i][2] += p*vf.z; acc[i][3] += p*vf.w;
        }
    }
    __syncthreads();                           // bufB free
    cpW(bufB, Wff, tid);
    __pipeline_commit();                       // g3: Wff -> bufB
    __pipeline_wait_prior(1);                  // g2 (S) done
    __syncthreads();

    {   // B2: + gate * Q @ S   [bufA]
        float u[4];
        #pragma unroll
        for (int i = 0; i < 4; i++) u[i] = (rl_s[gt*4+i] < 0) ? 1.f : 0.f;
        #pragma unroll 16
        for (int k = 0; k < 128; k++) {
            float4 sf = *(const float4*)&bufA[k*128 + gs*4];
            #pragma unroll
            for (int i = 0; i < 4; i++) {
                float q = Qs[(gt*4+i)*128 + k] * u[i];
                acc[i][0] += q*sf.x; acc[i][1] += q*sf.y;
                acc[i][2] += q*sf.z; acc[i][3] += q*sf.w;
            }
        }
    }

    // z = num/den + x  -> P
    #pragma unroll
    for (int i = 0; i < 4; i++) {
        int t_idx = gt*4 + i;
        int tg = cbase + tb + t_idx;
        float d = 1.f / den_s[t_idx];
        float4 xr = *(const float4*)&g_x[tg*H + gs*4];
        float4 r;
        r.x = acc[i][0]*d + xr.x; r.y = acc[i][1]*d + xr.y;
        r.z = acc[i][2]*d + xr.z; r.w = acc[i][3]*d + xr.w;
        *(float4*)&P[t_idx*128 + gs*4] = r;
    }
    __syncthreads();                           // bufA free, z published
    if (LAST) {
        cpW(bufA, Wout, tid);
        __pipeline_commit();                   // g4: Wout -> bufA
        __pipeline_wait_prior(1);              // g3 (Wff) done
    } else {
        __pipeline_wait_prior(0);
    }
    __syncthreads();

    {   // FF: x = leaky(z @ Wff^T + bff)   [bufB]
        float fa[4][4];
        mm32(fa, P, bufB, gt, gs);
        float4 bb = *(const float4*)&bff[gs*4];
        #pragma unroll
        for (int i = 0; i < 4; i++) {
            int tg = cbase + tb + gt*4 + i;
            float r[4] = {fa[i][0]+bb.x, fa[i][1]+bb.y, fa[i][2]+bb.z, fa[i][3]+bb.w};
            #pragma unroll
            for (int j = 0; j < 4; j++) r[j] = (r[j] > 0.f) ? r[j] : 0.01f*r[j];
            float4 rr = make_float4(r[0],r[1],r[2],r[3]);
            *(float4*)&g_x[tg*H + gs*4] = rr;
            if (LAST) *(float4*)&Qs[(gt*4+i)*128 + gs*4] = rr;
        }
    }
    if (LAST) {
        __pipeline_wait_prior(0);              // g4 (Wout) done
        __syncthreads();                       // x tile published in Qs
        float fa[4][4];
        mm32(fa, Qs, bufA, gt, gs);
        float4 bb = *(const float4*)&bout[gs*4];
        #pragma unroll
        for (int i = 0; i < 4; i++) {
            int tg = cbase + tb + gt*4 + i;
            *(float4*)&outp[tg*H + gs*4] =
                make_float4(fa[i][0]+bb.x, fa[i][1]+bb.y, fa[i][2]+bb.z, fa[i][3]+bb.w);
        }
    }
}

// ---------------- launch ------------------------------------------------------
extern "C" void kernel_launch(void* const* d_in, const int* in_sizes, int n_in,
                              void* d_out, int out_size) {
    const float* emb          = (const float*)d_in[0];
    const unsigned char* start= (const unsigned char*)d_in[1];
    const float* W_in         = (const float*)d_in[2];
    const float* b_in         = (const float*)d_in[3];
    const float* W_q          = (const float*)d_in[4];
    const float* W_k          = (const float*)d_in[5];
    const float* W_v          = (const float*)d_in[6];
    const float* W_ff         = (const float*)d_in[7];
    const float* b_ff         = (const float*)d_in[8];
    const float* W_out        = (const float*)d_in[9];
    const float* b_out        = (const float*)d_in[10];
    float* out = (float*)d_out;

    cudaFuncSetAttribute(qkv_kernel<1>, cudaFuncAttributeMaxDynamicSharedMemorySize, SMG);
    cudaFuncSetAttribute(qkv_kernel<0>, cudaFuncAttributeMaxDynamicSharedMemorySize, SMG);
    cudaFuncSetAttribute(attn_ff_kernel<0>, cudaFuncAttributeMaxDynamicSharedMemorySize, SMA);
    cudaFuncSetAttribute(attn_ff_kernel<1>, cudaFuncAttributeMaxDynamicSharedMemorySize, SMA);

    float *px, *pWt;
    cudaGetSymbolAddress((void**)&px, g_x);
    cudaGetSymbolAddress((void**)&pWt, g_Wt);

    prep_kernel<<<192, 256>>>(W_in, W_q, W_k, W_v, W_ff, W_out, start);

    // layer 0 (fused map_in)
    qkv_kernel<1><<<T/32, 256, SMG>>>(emb, pWt, b_in,
                                      pWt + 1*HH, pWt + 2*HH, pWt + 3*HH);
    chunk_kv_kernel<<<NC*4, 256>>>();
    scan_kernel<<<128, 128>>>();
    attn_ff_kernel<0><<<NC*4, 256, SMA>>>(pWt + 7*HH, b_ff, nullptr, nullptr, nullptr);

    // layer 1 (fused map_out)
    qkv_kernel<0><<<T/32, 256, SMG>>>(px, nullptr, nullptr,
                                      pWt + 4*HH, pWt + 5*HH, pWt + 6*HH);
    chunk_kv_kernel<<<NC*4, 256>>>();
    scan_kernel<<<128, 128>>>();
    attn_ff_kernel<1><<<NC*4, 256, SMA>>>(pWt + 8*HH, b_ff + H,
                                          pWt + 9*HH, b_out, out);
}

// round 6
// speedup vs baseline: 3.0970x; 1.0387x over previous
#include <cuda_runtime.h>
#include <cuda_pipeline.h>
#include <math.h>

#define T 4096
#define H 128
#define HH (H*H)
#define C 128
#define NC (T/C)   // 32
#define L 2

// ---------------- scratch (device globals; no allocation allowed) ------------
__device__ float g_x[T*H];
__device__ float g_q[T*H];
__device__ float g_k[T*H];
__device__ float g_kT[T*H];      // per-chunk transposed K: [c][k][s_local]
__device__ float g_v[T*H];
__device__ float g_Wt[10*HH];    // transposed weights [k][n]
__device__ float g_kvp[4*NC*HH]; // per-(chunk,quarter) KV partial sums
__device__ float g_S[NC*HH];     // state before each chunk
__device__ int   g_rloc[T];      // last reset index within chunk (local), -1 if none
__device__ int   g_cs0[NC];      // chunk tail-sum start (local)
__device__ int   g_crst[NC];     // chunk has reset flag

#define SMG ((2*HH + 32*128)*4)             // qkv: W0 + W1 + A tile   (144KB)
#define SMA ((2*HH + 2*32*128)*4)           // attn: bufA + bufB + Q + P (160KB)

// ---------------- prep: weight transpose + reset preprocessing ---------------
__global__ void prep_kernel(const float* __restrict__ W_in, const float* __restrict__ W_q,
                            const float* __restrict__ W_k, const float* __restrict__ W_v,
                            const float* __restrict__ W_ff, const float* __restrict__ W_out,
                            const unsigned char* __restrict__ start) {
    int b = blockIdx.x;
    int tid = threadIdx.x;
    if (b < 160) {
        __shared__ float tile[32][33];
        int z = b >> 4, sub = b & 15;
        const float* src;
        switch (z) {
            case 0: src = W_in; break;
            case 1: src = W_q; break;
            case 2: src = W_k; break;
            case 3: src = W_v; break;
            case 4: src = W_q + HH; break;
            case 5: src = W_k + HH; break;
            case 6: src = W_v + HH; break;
            case 7: src = W_ff; break;
            case 8: src = W_ff + HH; break;
            default: src = W_out; break;
        }
        float* dst = g_Wt + z*HH;
        int k0 = (sub >> 2)*32, n0 = (sub & 3)*32;
        int tx = tid & 31, ty = tid >> 5;    // (32,8)
        #pragma unroll
        for (int i = 0; i < 4; i++)
            tile[ty + 8*i][tx] = src[(n0 + ty + 8*i)*H + k0 + tx];
        __syncthreads();
        #pragma unroll
        for (int i = 0; i < 4; i++)
            dst[(k0 + ty + 8*i)*H + n0 + tx] = tile[tx][ty + 8*i];
    } else {
        __shared__ unsigned char f[C];
        int c = b - 160;
        if (tid < C) f[tid] = start[c*C + tid];
        __syncthreads();
        if (tid < C) {
            int r = -1;
            for (int j = tid; j >= 0; --j) { if (f[j]) { r = j; break; } }
            g_rloc[c*C + tid] = r;
            if (tid == C-1) { g_cs0[c] = (r >= 0) ? r : 0; g_crst[c] = (r >= 0) ? 1 : 0; }
        }
    }
}

// ---------------- async-copy helpers -----------------------------------------
__device__ __forceinline__ void cpW(float* Ws, const float* __restrict__ Wt, int tid) {
    #pragma unroll
    for (int it = 0; it < 16; it++) {
        int idx = (tid + it*256) * 4;
        __pipeline_memcpy_async(Ws + idx, Wt + idx, 16);
    }
}
__device__ __forceinline__ void cpA(float* As, const float* __restrict__ A, int tid) {
    #pragma unroll
    for (int it = 0; it < 4; it++) {
        int idx = (tid + it*256) * 4;
        __pipeline_memcpy_async(As + idx, A + idx, 16);
    }
}

// ---------------- shared GEMM microkernel ------------------------------------
__device__ __forceinline__ void mm32(float acc[4][4], const float* As, const float* Ws,
                                     int gt, int gs) {
    #pragma unroll
    for (int i = 0; i < 4; i++)
        #pragma unroll
        for (int j = 0; j < 4; j++) acc[i][j] = 0.f;
    #pragma unroll 16
    for (int k = 0; k < 128; k++) {
        float4 w = *(const float4*)&Ws[k*128 + gs*4];
        #pragma unroll
        for (int i = 0; i < 4; i++) {
            float a = As[(gt*4+i)*128 + k];
            acc[i][0] += a*w.x; acc[i][1] += a*w.y;
            acc[i][2] += a*w.z; acc[i][3] += a*w.w;
        }
    }
}

__device__ __forceinline__ float phi_f(float v) {
    return (v > 0.f) ? (1.f + v) : __expf(v);
}

// ---------------- fused [map_in] + QKV (cp.async double-buffered W) ----------
template<int FIRST>
__global__ __launch_bounds__(256) void qkv_kernel(const float* __restrict__ A0,
        const float* __restrict__ Wt_in, const float* __restrict__ b_in,
        const float* __restrict__ Wtq, const float* __restrict__ Wtk,
        const float* __restrict__ Wtv) {
    extern __shared__ float sm[];
    float* W0 = sm;               // [k][n] 128x128
    float* W1 = sm + HH;
    float* As = sm + 2*HH;        // [r][k] 32x128
    int tid = threadIdx.x;
    int t0 = blockIdx.x * 32;
    int gt = tid >> 5, gs = tid & 31;

    cpA(As, A0 + t0*H, tid);
    cpW(W0, FIRST ? Wt_in : Wtq, tid);
    __pipeline_commit();                       // g0: A + first W
    cpW(W1, FIRST ? Wtq : Wtk, tid);
    __pipeline_commit();                       // g1
    __pipeline_wait_prior(1);
    __syncthreads();

    if (FIRST) {   // x = emb @ W_in^T + b_in  (keep in As, write g_x)
        float acc[4][4];
        mm32(acc, As, W0, gt, gs);
        __syncthreads();                       // all reads of As/W0 done
        cpW(W0, Wtk, tid);
        __pipeline_commit();                   // g2: Wk -> W0
        float4 bb = *(const float4*)&b_in[gs*4];
        #pragma unroll
        for (int i = 0; i < 4; i++) {
            float4 r = make_float4(acc[i][0]+bb.x, acc[i][1]+bb.y,
                                   acc[i][2]+bb.z, acc[i][3]+bb.w);
            *(float4*)&As[(gt*4+i)*128 + gs*4] = r;
            *(float4*)&g_x[(t0 + gt*4+i)*H + gs*4] = r;
        }
        __pipeline_wait_prior(1);              // g1 (Wq in W1) done
        __syncthreads();
        {   // q = phi(x @ Wq^T)   [W1]
            float acc2[4][4];
            mm32(acc2, As, W1, gt, gs);
            #pragma unroll
            for (int i = 0; i < 4; i++)
                *(float4*)&g_q[(t0 + gt*4+i)*H + gs*4] =
                    make_float4(phi_f(acc2[i][0]), phi_f(acc2[i][1]),
                                phi_f(acc2[i][2]), phi_f(acc2[i][3]));
        }
        __syncthreads();                       // W1 free
        cpW(W1, Wtv, tid);
        __pipeline_commit();                   // g3: Wv -> W1
        __pipeline_wait_prior(1);              // g2 (Wk in W0) done
        __syncthreads();
        {   // k = phi(x @ Wk^T)   [W0]
            float acc2[4][4];
            mm32(acc2, As, W0, gt, gs);
            #pragma unroll
            for (int i = 0; i < 4; i++) {
                int t = t0 + gt*4 + i;
                float r[4] = {phi_f(acc2[i][0]), phi_f(acc2[i][1]),
                              phi_f(acc2[i][2]), phi_f(acc2[i][3])};
                *(float4*)&g_k[t*H + gs*4] = make_float4(r[0],r[1],r[2],r[3]);
                int cc = t >> 7, sl = t & 127;
                float* kT = g_kT + cc*HH + sl;
                #pragma unroll
                for (int j = 0; j < 4; j++) kT[(gs*4+j)*128] = r[j];
            }
        }
        __pipeline_wait_prior(0);              // g3 (Wv in W1) done
        __syncthreads();
        {   // v = x @ Wv^T        [W1]
            float acc2[4][4];
            mm32(acc2, As, W1, gt, gs);
            #pragma unroll
            for (int i = 0; i < 4; i++)
                *(float4*)&g_v[(t0 + gt*4+i)*H + gs*4] =
                    make_float4(acc2[i][0], acc2[i][1], acc2[i][2], acc2[i][3]);
        }
    } else {
        {   // q = phi(x @ Wq^T)   [W0]
            float acc[4][4];
            mm32(acc, As, W0, gt, gs);
            #pragma unroll
            for (int i = 0; i < 4; i++)
                *(float4*)&g_q[(t0 + gt*4+i)*H + gs*4] =
                    make_float4(phi_f(acc[i][0]), phi_f(acc[i][1]),
                                phi_f(acc[i][2]), phi_f(acc[i][3]));
        }
        __syncthreads();                       // W0 free
        cpW(W0, Wtv, tid);
        __pipeline_commit();                   // g2: Wv -> W0
        __pipeline_wait_prior(1);              // g1 (Wk in W1) done
        __syncthreads();
        {   // k = phi(x @ Wk^T)   [W1]
            float acc[4][4];
            mm32(acc, As, W1, gt, gs);
            #pragma unroll
            for (int i = 0; i < 4; i++) {
                int t = t0 + gt*4 + i;
                float r[4] = {phi_f(acc[i][0]), phi_f(acc[i][1]),
                              phi_f(acc[i][2]), phi_f(acc[i][3])};
                *(float4*)&g_k[t*H + gs*4] = make_float4(r[0],r[1],r[2],r[3]);
                int cc = t >> 7, sl = t & 127;
                float* kT = g_kT + cc*HH + sl;
                #pragma unroll
                for (int j = 0; j < 4; j++) kT[(gs*4+j)*128] = r[j];
            }
        }
        __pipeline_wait_prior(0);              // g2 (Wv in W0) done
        __syncthreads();
        {   // v = x @ Wv^T        [W0]
            float acc[4][4];
            mm32(acc, As, W0, gt, gs);
            #pragma unroll
            for (int i = 0; i < 4; i++)
                *(float4*)&g_v[(t0 + gt*4+i)*H + gs*4] =
                    make_float4(acc[i][0], acc[i][1], acc[i][2], acc[i][3]);
        }
    }
}

// ---------------- per-chunk-quarter KV partials: g_kvp = K_q^T @ V_q ---------
__global__ __launch_bounds__(256) void chunk_kv_kernel() {
    __shared__ float Ks[32*128];
    __shared__ float Vs[32*128];
    int bx = blockIdx.x;
    int c = bx >> 2, qi = bx & 3;
    int s0 = g_cs0[c];
    int tid = threadIdx.x;
    int base = (c*C + qi*32) * H;
    {
        const float4* K4 = (const float4*)(g_k + base);
        const float4* V4 = (const float4*)(g_v + base);
        float4* Ks4 = (float4*)Ks;
        float4* Vs4 = (float4*)Vs;
        #pragma unroll
        for (int it = 0; it < 4; it++) {
            int idx = tid + it*256;
            int srow = idx >> 5;
            float4 kv4 = K4[idx];
            if (qi*32 + srow < s0) kv4 = make_float4(0.f,0.f,0.f,0.f);
            Ks4[idx] = kv4;
            Vs4[idx] = V4[idx];
        }
    }
    __syncthreads();
    int ty = tid >> 4, tx = tid & 15;
    float acc[8][8] = {};
    #pragma unroll 4
    for (int s = 0; s < 32; s++) {
        float4 k0 = *(const float4*)&Ks[s*128 + ty*8];
        float4 k1 = *(const float4*)&Ks[s*128 + ty*8 + 4];
        float4 v0 = *(const float4*)&Vs[s*128 + tx*8];
        float4 v1 = *(const float4*)&Vs[s*128 + tx*8 + 4];
        float kf[8] = {k0.x,k0.y,k0.z,k0.w,k1.x,k1.y,k1.z,k1.w};
        float vf[8] = {v0.x,v0.y,v0.z,v0.w,v1.x,v1.y,v1.z,v1.w};
        #pragma unroll
        for (int i = 0; i < 8; i++)
            #pragma unroll
            for (int j = 0; j < 8; j++) acc[i][j] += kf[i]*vf[j];
    }
    float* dst = g_kvp + bx*HH;
    #pragma unroll
    for (int i = 0; i < 8; i++)
        #pragma unroll
        for (int j = 0; j < 2; j++)
            *(float4*)&dst[(ty*8+i)*128 + tx*8 + j*4] =
                make_float4(acc[i][j*4], acc[i][j*4+1], acc[i][j*4+2], acc[i][j*4+3]);
}

// ---------------- inter-chunk scan: two-level segmented monoid scan ----------
// 128 blocks x 512 threads. Each element e (16384 total) gets 4 threads,
// one per 8-chunk segment. Monoid: (kv, rst), comb(x,y)= (y.rst? y.kv : x.kv+y.kv, x.rst|y.rst)
__global__ __launch_bounds__(512) void scan_kernel() {
    __shared__ float ssum[4][128];
    __shared__ int   srst[4];      // per-segment reset flag (element-independent)
    __shared__ int   sc[NC];
    int tid = threadIdx.x;
    int seg = tid >> 7;            // 0..3
    int el  = tid & 127;
    int e   = blockIdx.x * 128 + el;
    if (tid < NC) sc[tid] = g_crst[tid];
    __syncthreads();

    // Phase 1: batched loads (32 in flight), quarter-reduce, local exclusive scan
    float v[8][4];
    int c0 = seg * 8;
    #pragma unroll
    for (int i = 0; i < 8; i++)
        #pragma unroll
        for (int q = 0; q < 4; q++)
            v[i][q] = g_kvp[((c0 + i)*4 + q)*HH + e];

    float kv[8];
    #pragma unroll
    for (int i = 0; i < 8; i++)
        kv[i] = (v[i][0] + v[i][1]) + (v[i][2] + v[i][3]);

    float pre_sum[8];
    int   pre_rst[8];
    float run = 0.f; int rrst = 0;
    #pragma unroll
    for (int i = 0; i < 8; i++) {
        pre_sum[i] = run; pre_rst[i] = rrst;
        int r = sc[c0 + i];
        run = r ? kv[i] : run + kv[i];
        rrst |= r;
    }
    ssum[seg][el] = run;
    if (el == 0) srst[seg] = rrst;
    __syncthreads();

    // Phase 2: fold segment aggregates < seg into base
    float base = 0.f;
    #pragma unroll
    for (int j = 0; j < 3; j++) {
        if (j < seg) {
            float as = ssum[j][el];
            base = srst[j] ? as : base + as;
        }
    }
    // Emit S_before[c]
    #pragma unroll
    for (int i = 0; i < 8; i++) {
        float S = pre_rst[i] ? pre_sum[i] : base + pre_sum[i];
        g_S[(c0 + i)*HH + e] = S;
    }
}

// ---------------- fused attn + FF [+ map_out] (double-buffered) ---------------
template<int LAST>
__global__ __launch_bounds__(256) void attn_ff_kernel(
        const float* __restrict__ Wff, const float* __restrict__ bff,
        const float* __restrict__ Wout, const float* __restrict__ bout,
        float* __restrict__ outp) {
    extern __shared__ float sm[];
    float* bufA = sm;              // 128x128: Kt -> S -> Wout
    float* bufB = sm + HH;         // 128x128: V -> Wff
    float* Qs   = sm + 2*HH;       // [t][k] 32x128
    float* P    = Qs + 32*128;     // [t][s] 32x128 (later z tile)
    __shared__ float den_s[32];
    __shared__ int rl_s[32];

    int bx = blockIdx.x;
    int c  = bx >> 2;
    int tb = (bx & 3) * 32;
    int cbase = c * C;
    int tid = threadIdx.x;
    int gt = tid >> 5, gs = tid & 31;

    if (tid < 32) rl_s[tid] = g_rloc[cbase + tb + tid];
    cpW(bufA, g_kT + c*HH, tid);
    cpA(Qs, g_q + (cbase + tb)*H, tid);
    __pipeline_commit();                       // g0: Kt + Q
    cpW(bufB, g_v + cbase*H, tid);
    __pipeline_commit();                       // g1: V
    __pipeline_wait_prior(1);
    __syncthreads();

    // Stage A: P[t][s] = q_t . k_s   [bufA = Kt]
    {
        float acc[4][4];
        mm32(acc, Qs, bufA, gt, gs);
        #pragma unroll
        for (int i = 0; i < 4; i++) {
            int t_idx = gt*4 + i;
            int tl = tb + t_idx;
            int rl = rl_s[t_idx];
            int lo = (rl < 0) ? 0 : rl;
            float pr[4];
            #pragma unroll
            for (int j = 0; j < 4; j++) {
                int s = gs*4 + j;
                float val = acc[i][j];
                if (s == tl) den_s[t_idx] = 1e-6f + val;
                pr[j] = (s >= lo && s <= tl) ? val : 0.f;
            }
            *(float4*)&P[t_idx*128 + gs*4] = make_float4(pr[0],pr[1],pr[2],pr[3]);
        }
    }
    __syncthreads();                           // bufA free, P published
    cpW(bufA, g_S + c*HH, tid);
    __pipeline_commit();                       // g2: S -> bufA
    __pipeline_wait_prior(1);                  // g1 (V) done
    __syncthreads();

    float acc[4][4] = {};
    #pragma unroll 16
    for (int s = 0; s < 128; s++) {            // B1: P @ V   [bufB]
        float4 vf = *(const float4*)&bufB[s*128 + gs*4];
        #pragma unroll
        for (int i = 0; i < 4; i++) {
            float p = P[(gt*4+i)*128 + s];
            acc[i][0] += p*vf.x; acc[i][1] += p*vf.y;
            acc[i][2] += p*vf.z; acc[i][3] += p*vf.w;
        }
    }
    __syncthreads();                           // bufB free
    cpW(bufB, Wff, tid);
    __pipeline_commit();                       // g3: Wff -> bufB
    __pipeline_wait_prior(1);                  // g2 (S) done
    __syncthreads();

    {   // B2: + gate * Q @ S   [bufA]
        float u[4];
        #pragma unroll
        for (int i = 0; i < 4; i++) u[i] = (rl_s[gt*4+i] < 0) ? 1.f : 0.f;
        #pragma unroll 16
        for (int k = 0; k < 128; k++) {
            float4 sf = *(const float4*)&bufA[k*128 + gs*4];
            #pragma unroll
            for (int i = 0; i < 4; i++) {
                float q = Qs[(gt*4+i)*128 + k] * u[i];
                acc[i][0] += q*sf.x; acc[i][1] += q*sf.y;
                acc[i][2] += q*sf.z; acc[i][3] += q*sf.w;
            }
        }
    }

    // z = num/den + x  -> P
    #pragma unroll
    for (int i = 0; i < 4; i++) {
        int t_idx = gt*4 + i;
        int tg = cbase + tb + t_idx;
        float d = 1.f / den_s[t_idx];
        float4 xr = *(const float4*)&g_x[tg*H + gs*4];
        float4 r;
        r.x = acc[i][0]*d + xr.x; r.y = acc[i][1]*d + xr.y;
        r.z = acc[i][2]*d + xr.z; r.w = acc[i][3]*d + xr.w;
        *(float4*)&P[t_idx*128 + gs*4] = r;
    }
    __syncthreads();                           // bufA free, z published
    if (LAST) {
        cpW(bufA, Wout, tid);
        __pipeline_commit();                   // g4: Wout -> bufA
        __pipeline_wait_prior(1);              // g3 (Wff) done
    } else {
        __pipeline_wait_prior(0);
    }
    __syncthreads();

    {   // FF: x = leaky(z @ Wff^T + bff)   [bufB]
        float fa[4][4];
        mm32(fa, P, bufB, gt, gs);
        float4 bb = *(const float4*)&bff[gs*4];
        #pragma unroll
        for (int i = 0; i < 4; i++) {
            int tg = cbase + tb + gt*4 + i;
            float r[4] = {fa[i][0]+bb.x, fa[i][1]+bb.y, fa[i][2]+bb.z, fa[i][3]+bb.w};
            #pragma unroll
            for (int j = 0; j < 4; j++) r[j] = (r[j] > 0.f) ? r[j] : 0.01f*r[j];
            float4 rr = make_float4(r[0],r[1],r[2],r[3]);
            *(float4*)&g_x[tg*H + gs*4] = rr;
            if (LAST) *(float4*)&Qs[(gt*4+i)*128 + gs*4] = rr;
        }
    }
    if (LAST) {
        __pipeline_wait_prior(0);              // g4 (Wout) done
        __syncthreads();                       // x tile published in Qs
        float fa[4][4];
        mm32(fa, Qs, bufA, gt, gs);
        float4 bb = *(const float4*)&bout[gs*4];
        #pragma unroll
        for (int i = 0; i < 4; i++) {
            int tg = cbase + tb + gt*4 + i;
            *(float4*)&outp[tg*H + gs*4] =
                make_float4(fa[i][0]+bb.x, fa[i][1]+bb.y, fa[i][2]+bb.z, fa[i][3]+bb.w);
        }
    }
}

// ---------------- launch ------------------------------------------------------
extern "C" void kernel_launch(void* const* d_in, const int* in_sizes, int n_in,
                              void* d_out, int out_size) {
    const float* emb          = (const float*)d_in[0];
    const unsigned char* start= (const unsigned char*)d_in[1];
    const float* W_in         = (const float*)d_in[2];
    const float* b_in         = (const float*)d_in[3];
    const float* W_q          = (const float*)d_in[4];
    const float* W_k          = (const float*)d_in[5];
    const float* W_v          = (const float*)d_in[6];
    const float* W_ff         = (const float*)d_in[7];
    const float* b_ff         = (const float*)d_in[8];
    const float* W_out        = (const float*)d_in[9];
    const float* b_out        = (const float*)d_in[10];
    float* out = (float*)d_out;

    cudaFuncSetAttribute(qkv_kernel<1>, cudaFuncAttributeMaxDynamicSharedMemorySize, SMG);
    cudaFuncSetAttribute(qkv_kernel<0>, cudaFuncAttributeMaxDynamicSharedMemorySize, SMG);
    cudaFuncSetAttribute(attn_ff_kernel<0>, cudaFuncAttributeMaxDynamicSharedMemorySize, SMA);
    cudaFuncSetAttribute(attn_ff_kernel<1>, cudaFuncAttributeMaxDynamicSharedMemorySize, SMA);

    float *px, *pWt;
    cudaGetSymbolAddress((void**)&px, g_x);
    cudaGetSymbolAddress((void**)&pWt, g_Wt);

    prep_kernel<<<192, 256>>>(W_in, W_q, W_k, W_v, W_ff, W_out, start);

    // layer 0 (fused map_in)
    qkv_kernel<1><<<T/32, 256, SMG>>>(emb, pWt, b_in,
                                      pWt + 1*HH, pWt + 2*HH, pWt + 3*HH);
    chunk_kv_kernel<<<NC*4, 256>>>();
    scan_kernel<<<128, 512>>>();
    attn_ff_kernel<0><<<NC*4, 256, SMA>>>(pWt + 7*HH, b_ff, nullptr, nullptr, nullptr);

    // layer 1 (fused map_out)
    qkv_kernel<0><<<T/32, 256, SMG>>>(px, nullptr, nullptr,
                                      pWt + 4*HH, pWt + 5*HH, pWt + 6*HH);
    chunk_kv_kernel<<<NC*4, 256>>>();
    scan_kernel<<<128, 512>>>();
    attn_ff_kernel<1><<<NC*4, 256, SMA>>>(pWt + 8*HH, b_ff + H,
                                          pWt + 9*HH, b_out, out);
}